// round 2
// baseline (speedup 1.0000x reference)
#include <cuda_runtime.h>

// Problem constants
#define PB 4
#define PN 8192
#define NPOINT 2048
#define PC 64
#define NS 32
#define SLOTS 33          // 1 (fps) + 32 samples
#define R2 (0.1f * 0.1f)
#define TPG (NPOINT * SLOTS)   // pairs per batch = 67584

// Scratch (device globals; no allocation allowed)
__device__ int   g_idx[PB * NPOINT * SLOTS];   // 1.08 MB
__device__ float g_ft[PB * PN * PC];           // 8 MB, features transposed to (B, N, C)

// ---------------------------------------------------------------------------
// Kernel 0: transpose features (B, C, N) -> (B, N, C)
// ---------------------------------------------------------------------------
__global__ __launch_bounds__(256) void transpose_kernel(const float* __restrict__ feat) {
    __shared__ float t[32][33];
    int b  = blockIdx.z;
    int n0 = blockIdx.x * 32;
    int c0 = blockIdx.y * 32;
    int tx = threadIdx.x;   // 0..31
    int ty = threadIdx.y;   // 0..7
    const float* fb = feat + (size_t)b * PC * PN;
#pragma unroll
    for (int i = 0; i < 32; i += 8)
        t[ty + i][tx] = fb[(size_t)(c0 + ty + i) * PN + n0 + tx];
    __syncthreads();
    float* ob = g_ft + (size_t)b * PN * PC;
#pragma unroll
    for (int i = 0; i < 32; i += 8)
        ob[(size_t)(n0 + ty + i) * PC + c0 + tx] = t[tx][ty + i];
}

// ---------------------------------------------------------------------------
// Kernel 1: ball query. One warp per centroid, 16 warps/block sharing point tiles.
// Collects up to 32 in-radius indices in ascending scan order; pads with
// first hit (or 0 if empty); prepends fps_idx.
// ---------------------------------------------------------------------------
#define BQ_WARPS 16
#define TILE 1024

__global__ __launch_bounds__(BQ_WARPS * 32) void ballquery_kernel(
    const float* __restrict__ xyz, const float* __restrict__ new_xyz,
    const int* __restrict__ fps_idx) {
    __shared__ float4 tile[TILE];
    __shared__ int    slots[BQ_WARPS][NS];
    __shared__ int    ndone;

    int tid  = threadIdx.x;
    int w    = tid >> 5;
    int lane = tid & 31;
    int gc   = blockIdx.x * BQ_WARPS + w;   // global centroid id in [0, B*NPOINT)
    int b    = gc / NPOINT;                 // uniform per block (2048 % 16 == 0)

    float cx = new_xyz[gc * 3 + 0];
    float cy = new_xyz[gc * 3 + 1];
    float cz = new_xyz[gc * 3 + 2];

    if (tid == 0) ndone = 0;
    int cnt = 0;
    const float* xb = xyz + (size_t)b * PN * 3;

    for (int ts = 0; ts < PN; ts += TILE) {
        __syncthreads();                 // covers ndone init + prior-iter updates
        if (ndone == BQ_WARPS) break;    // uniform
        for (int i = tid; i < TILE; i += BQ_WARPS * 32) {
            int p = ts + i;
            tile[i] = make_float4(xb[p * 3 + 0], xb[p * 3 + 1], xb[p * 3 + 2], 0.f);
        }
        __syncthreads();
        if (cnt < NS) {
            for (int cb = 0; cb < TILE; cb += 32) {
                float4 p = tile[cb + lane];
                float dx = cx - p.x, dy = cy - p.y, dz = cz - p.z;
                // Match XLA's unfused left-to-right sum exactly (no FMA contraction):
                float d2 = __fadd_rn(__fadd_rn(__fmul_rn(dx, dx), __fmul_rn(dy, dy)),
                                     __fmul_rn(dz, dz));
                bool valid = d2 < R2;
                unsigned mask = __ballot_sync(0xFFFFFFFFu, valid);
                if (valid) {
                    int pos = cnt + __popc(mask & ((1u << lane) - 1u));
                    if (pos < NS) slots[w][pos] = ts + cb + lane;
                }
                cnt += __popc(mask);
                if (cnt >= NS) break;
            }
            if (cnt >= NS && lane == 0) atomicAdd(&ndone, 1);
        }
    }
    __syncwarp();
    int pad = (cnt > 0) ? slots[w][0] : 0;
    int v   = (lane < cnt) ? slots[w][lane] : pad;
    int base = gc * SLOTS;
    if (lane == 0) g_idx[base] = fps_idx[gc];
    g_idx[base + 1 + lane] = v;
}

// ---------------------------------------------------------------------------
// Kernel 2: gather + center + concat.
// Output (B, 70, NPOINT, 33): ch 0-2 centered xyz, 3-5 centered xyz (dup),
// 6-69 gathered features. Block handles 64 linear (j,s) pairs of one batch;
// stages feature vectors in smem so both gathers (256B contiguous) and
// writes (per-channel 256B runs) are coalesced.
// ---------------------------------------------------------------------------
#define GP 64
#define BPB (TPG / GP)   // 1056 blocks per batch

__global__ __launch_bounds__(256) void gather_kernel(
    const float* __restrict__ xyz, const float* __restrict__ new_xyz,
    float* __restrict__ out) {
    __shared__ float feat[GP][PC + 1];
    __shared__ float cent[3][GP];
    __shared__ int   sidx[GP];

    int bb  = blockIdx.x / BPB;
    int t0  = (blockIdx.x % BPB) * GP;
    int tid = threadIdx.x;

    if (tid < GP) {
        int t = t0 + tid;
        int j = t / SLOTS;
        int s = t - j * SLOTS;
        int iv = g_idx[(bb * NPOINT + j) * SLOTS + s];
        sidx[tid] = iv;
        const float* nz = new_xyz + ((size_t)bb * NPOINT + j) * 3;
        const float* pz = xyz + ((size_t)bb * PN + iv) * 3;
        cent[0][tid] = pz[0] - nz[0];
        cent[1][tid] = pz[1] - nz[1];
        cent[2][tid] = pz[2] - nz[2];
    }
    __syncthreads();

    const float* ftb = g_ft + (size_t)bb * PN * PC;
    for (int k = tid; k < GP * PC; k += 256) {
        int pair = k >> 6;
        int ch   = k & 63;
        feat[pair][ch] = ftb[(size_t)sidx[pair] * PC + ch];
    }
    __syncthreads();

    float* ob = out + (size_t)bb * 70 * TPG + t0;
    for (int k = tid; k < 70 * GP; k += 256) {
        int c    = k >> 6;
        int pair = k & 63;
        float v = (c < 6) ? cent[c % 3][pair] : feat[pair][c - 6];
        ob[(size_t)c * TPG + pair] = v;
    }
}

// ---------------------------------------------------------------------------
extern "C" void kernel_launch(void* const* d_in, const int* in_sizes, int n_in,
                              void* d_out, int out_size) {
    const float* xyz      = (const float*)d_in[0];   // (B, N, 3)
    const float* new_xyz  = (const float*)d_in[1];   // (B, NPOINT, 3)
    const float* features = (const float*)d_in[2];   // (B, C, N)
    const int*   fps_idx  = (const int*)d_in[3];     // (B, NPOINT)
    float* out = (float*)d_out;                      // (B, 70, NPOINT, 33)

    transpose_kernel<<<dim3(PN / 32, PC / 32, PB), dim3(32, 8)>>>(features);
    ballquery_kernel<<<(PB * NPOINT) / BQ_WARPS, BQ_WARPS * 32>>>(xyz, new_xyz, fps_idx);
    gather_kernel<<<PB * BPB, 256>>>(xyz, new_xyz, out);
}

// round 3
// speedup vs baseline: 1.7608x; 1.7608x over previous
#include <cuda_runtime.h>

// Problem constants
#define PB 4
#define PN 8192
#define NPOINT 2048
#define PC 64
#define NS 32
#define SLOTS 33               // 1 (fps) + 32 samples
#define R2 (0.1f * 0.1f)
#define TPG (NPOINT * SLOTS)   // pairs per batch = 67584

#define GRID 10
#define NC (GRID * GRID * GRID)   // 1000 cells per batch

// Scratch (device globals; no allocation allowed)
__device__ int    g_idx[PB * NPOINT * SLOTS];   // 1.08 MB
__device__ float  g_ft[PB * PN * PC];           // 8 MB, features transposed (B, N, C)
__device__ int    g_cellcnt[PB][NC];
__device__ int    g_cellstart[PB][NC + 1];
__device__ int    g_cellcur[PB][NC];
__device__ float4 g_pts[PB * PN];               // cell-sorted coords, idx in .w

__device__ __forceinline__ int cell_of(float x) {
    int c = (int)(x * 10.0f);
    return min(max(c, 0), GRID - 1);
}

// ---------------------------------------------------------------------------
// Kernel 0: transpose features (B, C, N) -> (B, N, C)
// ---------------------------------------------------------------------------
__global__ __launch_bounds__(256) void transpose_kernel(const float* __restrict__ feat) {
    __shared__ float t[32][33];
    int b  = blockIdx.z;
    int n0 = blockIdx.x * 32;
    int c0 = blockIdx.y * 32;
    int tx = threadIdx.x;   // 0..31
    int ty = threadIdx.y;   // 0..7
    const float* fb = feat + (size_t)b * PC * PN;
#pragma unroll
    for (int i = 0; i < 32; i += 8)
        t[ty + i][tx] = fb[(size_t)(c0 + ty + i) * PN + n0 + tx];
    __syncthreads();
    float* ob = g_ft + (size_t)b * PN * PC;
#pragma unroll
    for (int i = 0; i < 32; i += 8)
        ob[(size_t)(n0 + ty + i) * PC + c0 + tx] = t[tx][ty + i];
}

// ---------------------------------------------------------------------------
// Grid build: zero -> histogram -> per-batch scan -> scatter (counting sort)
// ---------------------------------------------------------------------------
__global__ __launch_bounds__(256) void zero_kernel() {
    int i = blockIdx.x * 256 + threadIdx.x;
    if (i < PB * NC) ((int*)g_cellcnt)[i] = 0;
}

__global__ __launch_bounds__(256) void hist_kernel(const float* __restrict__ xyz) {
    int i = blockIdx.x * 256 + threadIdx.x;   // 0 .. PB*PN
    int b = i >> 13;
    float x = xyz[i * 3 + 0], y = xyz[i * 3 + 1], z = xyz[i * 3 + 2];
    int c = (cell_of(z) * GRID + cell_of(y)) * GRID + cell_of(x);
    atomicAdd(&g_cellcnt[b][c], 1);
}

__global__ __launch_bounds__(1024) void scan_kernel() {
    __shared__ int s[1024];
    int b = blockIdx.x, t = threadIdx.x;
    int v = (t < NC) ? g_cellcnt[b][t] : 0;
    s[t] = v;
    __syncthreads();
#pragma unroll
    for (int off = 1; off < 1024; off <<= 1) {
        int x = (t >= off) ? s[t - off] : 0;
        __syncthreads();
        s[t] += x;
        __syncthreads();
    }
    if (t < NC) {
        int incl = s[t];
        g_cellstart[b][t + 1] = incl;       // t=999 writes [1000] = PN
        g_cellcur[b][t]       = incl - v;   // exclusive start
        if (t == 0) g_cellstart[b][0] = 0;
    }
}

__global__ __launch_bounds__(256) void scatter_kernel(const float* __restrict__ xyz) {
    int i = blockIdx.x * 256 + threadIdx.x;
    int b = i >> 13, p = i & (PN - 1);
    float x = xyz[i * 3 + 0], y = xyz[i * 3 + 1], z = xyz[i * 3 + 2];
    int c = (cell_of(z) * GRID + cell_of(y)) * GRID + cell_of(x);
    int pos = atomicAdd(&g_cellcur[b][c], 1);
    g_pts[(b << 13) + pos] = make_float4(x, y, z, __int_as_float(p));
}

// ---------------------------------------------------------------------------
// Warp bitonic sort of NR*32 ints (ascending), lane-major layout j = k*32+lane.
// ---------------------------------------------------------------------------
template <int NR>
__device__ __forceinline__ void bsort(int* r, int lane) {
    const int TOT = NR * 32;
#pragma unroll
    for (int size = 2; size <= TOT; size <<= 1) {
#pragma unroll
        for (int stride = size >> 1; stride > 0; stride >>= 1) {
            if (stride >= 32) {
                int ks = stride >> 5;
#pragma unroll
                for (int k = 0; k < NR; k++) {
                    if ((k & ks) == 0) {
                        int j = k * 32 + lane;
                        bool desc = (j & size) != 0;
                        int a = r[k], c = r[k + ks];
                        int lo = min(a, c), hi = max(a, c);
                        r[k]      = desc ? hi : lo;
                        r[k + ks] = desc ? lo : hi;
                    }
                }
            } else {
#pragma unroll
                for (int k = 0; k < NR; k++) {
                    int j = k * 32 + lane;
                    bool desc  = (j & size) != 0;
                    int  p     = __shfl_xor_sync(0xFFFFFFFFu, r[k], stride);
                    bool lower = (lane & stride) == 0;
                    r[k] = (lower != desc) ? min(r[k], p) : max(r[k], p);
                }
            }
        }
    }
}

// ---------------------------------------------------------------------------
// Kernel 1: grid ball query. One warp per centroid; scans <= 27 neighbor cells
// (x-contiguous rows), collects in-radius candidates, sorts ascending, takes
// the 32 smallest (exact reference semantics), pads with first / 0.
// ---------------------------------------------------------------------------
#define BQ_WARPS 8

__global__ __launch_bounds__(BQ_WARPS * 32) void ballquery_grid_kernel(
    const float* __restrict__ new_xyz, const int* __restrict__ fps_idx) {
    __shared__ int slots[BQ_WARPS][128];

    int tid  = threadIdx.x;
    int w    = tid >> 5;
    int lane = tid & 31;
    int gc   = blockIdx.x * BQ_WARPS + w;   // centroid id in [0, B*NPOINT)
    int b    = gc / NPOINT;

    float cx = new_xyz[gc * 3 + 0];
    float cy = new_xyz[gc * 3 + 1];
    float cz = new_xyz[gc * 3 + 2];

    int icx = cell_of(cx), icy = cell_of(cy), icz = cell_of(cz);
    int xlo = max(icx - 1, 0), xhi = min(icx + 1, GRID - 1);
    int ylo = max(icy - 1, 0), yhi = min(icy + 1, GRID - 1);
    int zlo = max(icz - 1, 0), zhi = min(icz + 1, GRID - 1);

    const int*    cs  = g_cellstart[b];
    const float4* pts = g_pts + ((size_t)b << 13);

    int cnt = 0;
    for (int z = zlo; z <= zhi; z++) {
        for (int y = ylo; y <= yhi; y++) {
            int rowbase = (z * GRID + y) * GRID;
            int s = cs[rowbase + xlo];
            int e = cs[rowbase + xhi + 1];
            for (int base = s; base < e; base += 32) {
                int  i   = base + lane;
                bool inr = i < e;
                float4 p = inr ? pts[i] : make_float4(1e9f, 1e9f, 1e9f, 0.f);
                float dx = cx - p.x, dy = cy - p.y, dz = cz - p.z;
                // Match XLA's unfused left-to-right sum exactly (no FMA):
                float d2 = __fadd_rn(__fadd_rn(__fmul_rn(dx, dx), __fmul_rn(dy, dy)),
                                     __fmul_rn(dz, dz));
                bool valid = inr && (d2 < R2);
                unsigned m = __ballot_sync(0xFFFFFFFFu, valid);
                if (valid) {
                    int pos = cnt + __popc(m & ((1u << lane) - 1u));
                    if (pos < 128) slots[w][pos] = __float_as_int(p.w);
                }
                cnt += __popc(m);
            }
        }
    }
    __syncwarp();

    int cl = min(cnt, 128);
    int r[4];
#pragma unroll
    for (int k = 0; k < 4; k++) {
        int j = k * 32 + lane;
        r[k] = (j < cl) ? slots[w][j] : 0x7FFFFFFF;
    }
    if (cnt <= 32)      bsort<1>(r, lane);
    else if (cnt <= 64) bsort<2>(r, lane);
    else                bsort<4>(r, lane);

    int first = __shfl_sync(0xFFFFFFFFu, r[0], 0);
    int pad   = (cnt > 0) ? first : 0;
    int v     = (lane < cnt) ? r[0] : pad;

    int base = gc * SLOTS;
    if (lane == 0) g_idx[base] = fps_idx[gc];
    g_idx[base + 1 + lane] = v;
}

// ---------------------------------------------------------------------------
// Kernel 2: gather + center + concat.
// Output (B, 70, NPOINT, 33): ch 0-2 centered xyz, 3-5 dup, 6-69 features.
// ---------------------------------------------------------------------------
#define GP 64
#define BPB (TPG / GP)   // 1056 blocks per batch

__global__ __launch_bounds__(256) void gather_kernel(
    const float* __restrict__ xyz, const float* __restrict__ new_xyz,
    float* __restrict__ out) {
    __shared__ float feat[GP][PC + 1];
    __shared__ float cent[3][GP];
    __shared__ int   sidx[GP];

    int bb  = blockIdx.x / BPB;
    int t0  = (blockIdx.x % BPB) * GP;
    int tid = threadIdx.x;

    if (tid < GP) {
        int t = t0 + tid;
        int j = t / SLOTS;
        int s = t - j * SLOTS;
        int iv = g_idx[(bb * NPOINT + j) * SLOTS + s];
        sidx[tid] = iv;
        const float* nz = new_xyz + ((size_t)bb * NPOINT + j) * 3;
        const float* pz = xyz + ((size_t)bb * PN + iv) * 3;
        cent[0][tid] = pz[0] - nz[0];
        cent[1][tid] = pz[1] - nz[1];
        cent[2][tid] = pz[2] - nz[2];
    }
    __syncthreads();

    const float* ftb = g_ft + (size_t)bb * PN * PC;
    for (int k = tid; k < GP * PC; k += 256) {
        int pair = k >> 6;
        int ch   = k & 63;
        feat[pair][ch] = ftb[(size_t)sidx[pair] * PC + ch];
    }
    __syncthreads();

    float* ob = out + (size_t)bb * 70 * TPG + t0;
    for (int k = tid; k < 70 * GP; k += 256) {
        int c    = k >> 6;
        int pair = k & 63;
        float v = (c < 6) ? cent[c % 3][pair] : feat[pair][c - 6];
        ob[(size_t)c * TPG + pair] = v;
    }
}

// ---------------------------------------------------------------------------
extern "C" void kernel_launch(void* const* d_in, const int* in_sizes, int n_in,
                              void* d_out, int out_size) {
    const float* xyz      = (const float*)d_in[0];   // (B, N, 3)
    const float* new_xyz  = (const float*)d_in[1];   // (B, NPOINT, 3)
    const float* features = (const float*)d_in[2];   // (B, C, N)
    const int*   fps_idx  = (const int*)d_in[3];     // (B, NPOINT)
    float* out = (float*)d_out;                      // (B, 70, NPOINT, 33)

    transpose_kernel<<<dim3(PN / 32, PC / 32, PB), dim3(32, 8)>>>(features);
    zero_kernel<<<(PB * NC + 255) / 256, 256>>>();
    hist_kernel<<<(PB * PN) / 256, 256>>>(xyz);
    scan_kernel<<<PB, 1024>>>();
    scatter_kernel<<<(PB * PN) / 256, 256>>>(xyz);
    ballquery_grid_kernel<<<(PB * NPOINT) / BQ_WARPS, BQ_WARPS * 32>>>(new_xyz, fps_idx);
    gather_kernel<<<PB * BPB, 256>>>(xyz, new_xyz, out);
}

// round 4
// speedup vs baseline: 2.1110x; 1.1988x over previous
#include <cuda_runtime.h>

// Problem constants
#define PB 4
#define PN 8192
#define NPOINT 2048
#define PC 64
#define NS 32
#define SLOTS 33               // 1 (fps) + 32 samples
#define R2 (0.1f * 0.1f)
#define TPG (NPOINT * SLOTS)   // pairs per batch = 67584

#define GRID 10
#define NC (GRID * GRID * GRID)   // 1000 cells per batch

// Scratch (device globals; no allocation allowed)
__device__ int    g_idx[PB * NPOINT * SLOTS];   // 1.08 MB
__device__ float  g_ft[PB * PN * PC];           // 8 MB, features transposed (B, N, C)
__device__ int    g_cellstart[PB][NC + 1];
__device__ float4 g_pts[PB * PN];               // cell-sorted coords, idx in .w

__device__ __forceinline__ int cell_of(float x) {
    int c = (int)(x * 10.0f);
    return min(max(c, 0), GRID - 1);
}

// ---------------------------------------------------------------------------
// Kernel 0: transpose features (B, C, N) -> (B, N, C)
// ---------------------------------------------------------------------------
__global__ __launch_bounds__(256) void transpose_kernel(const float* __restrict__ feat) {
    __shared__ float t[32][33];
    int b  = blockIdx.z;
    int n0 = blockIdx.x * 32;
    int c0 = blockIdx.y * 32;
    int tx = threadIdx.x;   // 0..31
    int ty = threadIdx.y;   // 0..7
    const float* fb = feat + (size_t)b * PC * PN;
#pragma unroll
    for (int i = 0; i < 32; i += 8)
        t[ty + i][tx] = fb[(size_t)(c0 + ty + i) * PN + n0 + tx];
    __syncthreads();
    float* ob = g_ft + (size_t)b * PN * PC;
#pragma unroll
    for (int i = 0; i < 32; i += 8)
        ob[(size_t)(n0 + ty + i) * PC + c0 + tx] = t[tx][ty + i];
}

// ---------------------------------------------------------------------------
// Kernel 1: fused grid build. One block per batch: histogram (smem atomics),
// two-level warp-shuffle scan, scatter from registers. Replaces 4 kernels.
// ---------------------------------------------------------------------------
__global__ __launch_bounds__(1024) void grid_build_kernel(const float* __restrict__ xyz) {
    __shared__ int hist[NC];   // doubles as running cursor after scan
    __shared__ int wsum[32];

    int b = blockIdx.x, t = threadIdx.x;
    int lane = t & 31, w = t >> 5;

    for (int i = t; i < NC; i += 1024) hist[i] = 0;
    __syncthreads();

    // Read 8 points/thread (coalesced), histogram via smem atomics.
    const float* xb = xyz + (size_t)b * PN * 3;
    float px[8], py[8], pz[8];
    int   pc[8];
#pragma unroll
    for (int k = 0; k < 8; k++) {
        int i = t + k * 1024;
        px[k] = xb[i * 3 + 0];
        py[k] = xb[i * 3 + 1];
        pz[k] = xb[i * 3 + 2];
        pc[k] = (cell_of(pz[k]) * GRID + cell_of(py[k])) * GRID + cell_of(px[k]);
        atomicAdd(&hist[pc[k]], 1);
    }
    __syncthreads();

    // Two-level inclusive scan of hist[0..NC).
    int v = (t < NC) ? hist[t] : 0;
    int s = v;
#pragma unroll
    for (int off = 1; off < 32; off <<= 1) {
        int u = __shfl_up_sync(0xFFFFFFFFu, s, off);
        if (lane >= off) s += u;
    }
    if (lane == 31) wsum[w] = s;
    __syncthreads();
    if (w == 0) {
        int ws = wsum[lane];
#pragma unroll
        for (int off = 1; off < 32; off <<= 1) {
            int u = __shfl_up_sync(0xFFFFFFFFu, ws, off);
            if (lane >= off) ws += u;
        }
        wsum[lane] = ws;
    }
    __syncthreads();
    int incl = s + (w > 0 ? wsum[w - 1] : 0);
    int excl = incl - v;
    __syncthreads();          // all reads of hist done before cursor overwrite
    if (t < NC) {
        g_cellstart[b][t + 1] = incl;
        if (t == 0) g_cellstart[b][0] = 0;
        hist[t] = excl;       // reuse as scatter cursor
    }
    __syncthreads();

    // Scatter from registers.
    float4* pout = g_pts + ((size_t)b << 13);
#pragma unroll
    for (int k = 0; k < 8; k++) {
        int pos = atomicAdd(&hist[pc[k]], 1);
        pout[pos] = make_float4(px[k], py[k], pz[k], __int_as_float(t + k * 1024));
    }
}

// ---------------------------------------------------------------------------
// Warp bitonic sort of NR*32 ints (ascending), lane-major layout j = k*32+lane.
// ---------------------------------------------------------------------------
template <int NR>
__device__ __forceinline__ void bsort(int* r, int lane) {
    const int TOT = NR * 32;
#pragma unroll
    for (int size = 2; size <= TOT; size <<= 1) {
#pragma unroll
        for (int stride = size >> 1; stride > 0; stride >>= 1) {
            if (stride >= 32) {
                int ks = stride >> 5;
#pragma unroll
                for (int k = 0; k < NR; k++) {
                    if ((k & ks) == 0) {
                        int j = k * 32 + lane;
                        bool desc = (j & size) != 0;
                        int a = r[k], c = r[k + ks];
                        int lo = min(a, c), hi = max(a, c);
                        r[k]      = desc ? hi : lo;
                        r[k + ks] = desc ? lo : hi;
                    }
                }
            } else {
#pragma unroll
                for (int k = 0; k < NR; k++) {
                    int j = k * 32 + lane;
                    bool desc  = (j & size) != 0;
                    int  p     = __shfl_xor_sync(0xFFFFFFFFu, r[k], stride);
                    bool lower = (lane & stride) == 0;
                    r[k] = (lower != desc) ? min(r[k], p) : max(r[k], p);
                }
            }
        }
    }
}

// ---------------------------------------------------------------------------
// Kernel 2: grid ball query. One warp per centroid; scans <= 27 neighbor cells
// (x-contiguous rows), collects candidates, sorts ascending, takes 32 smallest.
// ---------------------------------------------------------------------------
#define BQ_WARPS 8

__global__ __launch_bounds__(BQ_WARPS * 32) void ballquery_grid_kernel(
    const float* __restrict__ new_xyz, const int* __restrict__ fps_idx) {
    __shared__ int slots[BQ_WARPS][128];

    int tid  = threadIdx.x;
    int w    = tid >> 5;
    int lane = tid & 31;
    int gc   = blockIdx.x * BQ_WARPS + w;   // centroid id in [0, B*NPOINT)
    int b    = gc / NPOINT;

    float cx = new_xyz[gc * 3 + 0];
    float cy = new_xyz[gc * 3 + 1];
    float cz = new_xyz[gc * 3 + 2];

    int icx = cell_of(cx), icy = cell_of(cy), icz = cell_of(cz);
    int xlo = max(icx - 1, 0), xhi = min(icx + 1, GRID - 1);
    int ylo = max(icy - 1, 0), yhi = min(icy + 1, GRID - 1);
    int zlo = max(icz - 1, 0), zhi = min(icz + 1, GRID - 1);

    const int*    cs  = g_cellstart[b];
    const float4* pts = g_pts + ((size_t)b << 13);

    int cnt = 0;
    for (int z = zlo; z <= zhi; z++) {
        for (int y = ylo; y <= yhi; y++) {
            int rowbase = (z * GRID + y) * GRID;
            int s = cs[rowbase + xlo];
            int e = cs[rowbase + xhi + 1];
            for (int base = s; base < e; base += 32) {
                int  i   = base + lane;
                bool inr = i < e;
                float4 p = inr ? pts[i] : make_float4(1e9f, 1e9f, 1e9f, 0.f);
                float dx = cx - p.x, dy = cy - p.y, dz = cz - p.z;
                // Match XLA's unfused left-to-right sum exactly (no FMA):
                float d2 = __fadd_rn(__fadd_rn(__fmul_rn(dx, dx), __fmul_rn(dy, dy)),
                                     __fmul_rn(dz, dz));
                bool valid = inr && (d2 < R2);
                unsigned m = __ballot_sync(0xFFFFFFFFu, valid);
                if (valid) {
                    int pos = cnt + __popc(m & ((1u << lane) - 1u));
                    if (pos < 128) slots[w][pos] = __float_as_int(p.w);
                }
                cnt += __popc(m);
            }
        }
    }
    __syncwarp();

    int cl = min(cnt, 128);
    int r[4];
#pragma unroll
    for (int k = 0; k < 4; k++) {
        int j = k * 32 + lane;
        r[k] = (j < cl) ? slots[w][j] : 0x7FFFFFFF;
    }
    if (cnt <= 32)      bsort<1>(r, lane);
    else if (cnt <= 64) bsort<2>(r, lane);
    else                bsort<4>(r, lane);

    int first = __shfl_sync(0xFFFFFFFFu, r[0], 0);
    int pad   = (cnt > 0) ? first : 0;
    int v     = (lane < cnt) ? r[0] : pad;

    int base = gc * SLOTS;
    if (lane == 0) g_idx[base] = fps_idx[gc];
    g_idx[base + 1 + lane] = v;
}

// ---------------------------------------------------------------------------
// Kernel 3: gather + center + concat, float4 I/O.
// Output (B, 70, NPOINT, 33): ch 0-2 centered xyz, 3-5 dup, 6-69 features.
// Stages features TRANSPOSED in smem (ft[ch][pair]) so output-side reads and
// the 128-bit global stores are both friendly.
// ---------------------------------------------------------------------------
#define GP 64
#define GPAD 65
#define BPB (TPG / GP)   // 1056 blocks per batch

__global__ __launch_bounds__(256) void gather_kernel(
    const float* __restrict__ xyz, const float* __restrict__ new_xyz,
    float* __restrict__ out) {
    __shared__ float ft[PC][GPAD];     // transposed staging: ft[ch][pair]
    __shared__ float cent[3][GP];
    __shared__ int   sidx[GP];

    int bb  = blockIdx.x / BPB;
    int t0  = (blockIdx.x % BPB) * GP;
    int tid = threadIdx.x;

    if (tid < GP) {
        int t = t0 + tid;
        int j = t / SLOTS;
        int s = t - j * SLOTS;
        int iv = g_idx[(bb * NPOINT + j) * SLOTS + s];
        sidx[tid] = iv;
        const float* nz = new_xyz + ((size_t)bb * NPOINT + j) * 3;
        const float* pz = xyz + ((size_t)bb * PN + iv) * 3;
        cent[0][tid] = pz[0] - nz[0];
        cent[1][tid] = pz[1] - nz[1];
        cent[2][tid] = pz[2] - nz[2];
    }
    __syncthreads();

    // Stage: 64 pairs x 16 float4 (contiguous 256B per pair), transpose into smem.
    const float4* ftb4 = (const float4*)(g_ft + (size_t)bb * PN * PC);
    for (int k = tid; k < GP * 16; k += 256) {
        int pair = k >> 4;
        int q    = k & 15;
        float4 f = ftb4[(size_t)sidx[pair] * 16 + q];
        ft[4 * q + 0][pair] = f.x;
        ft[4 * q + 1][pair] = f.y;
        ft[4 * q + 2][pair] = f.z;
        ft[4 * q + 3][pair] = f.w;
    }
    __syncthreads();

    // Write: 70 channels x 16 float4 per block, 128-bit stores.
    float* ob = out + (size_t)bb * 70 * TPG + t0;
    for (int k = tid; k < 70 * 16; k += 256) {
        int c = k >> 4;
        int q = k & 15;
        float4 v;
        if (c < 6) {
            const float* a = cent[c < 3 ? c : c - 3];
            v = make_float4(a[4 * q], a[4 * q + 1], a[4 * q + 2], a[4 * q + 3]);
        } else {
            const float* a = ft[c - 6];
            v = make_float4(a[4 * q], a[4 * q + 1], a[4 * q + 2], a[4 * q + 3]);
        }
        *(float4*)(ob + (size_t)c * TPG + 4 * q) = v;
    }
}

// ---------------------------------------------------------------------------
extern "C" void kernel_launch(void* const* d_in, const int* in_sizes, int n_in,
                              void* d_out, int out_size) {
    const float* xyz      = (const float*)d_in[0];   // (B, N, 3)
    const float* new_xyz  = (const float*)d_in[1];   // (B, NPOINT, 3)
    const float* features = (const float*)d_in[2];   // (B, C, N)
    const int*   fps_idx  = (const int*)d_in[3];     // (B, NPOINT)
    float* out = (float*)d_out;                      // (B, 70, NPOINT, 33)

    transpose_kernel<<<dim3(PN / 32, PC / 32, PB), dim3(32, 8)>>>(features);
    grid_build_kernel<<<PB, 1024>>>(xyz);
    ballquery_grid_kernel<<<(PB * NPOINT) / BQ_WARPS, BQ_WARPS * 32>>>(new_xyz, fps_idx);
    gather_kernel<<<PB * BPB, 256>>>(xyz, new_xyz, out);
}

// round 5
// speedup vs baseline: 2.2349x; 1.0587x over previous
#include <cuda_runtime.h>

// Problem constants
#define PB 4
#define PN 8192
#define NPOINT 2048
#define PC 64
#define NS 32
#define SLOTS 33               // 1 (fps) + 32 samples
#define R2 (0.1f * 0.1f)
#define TPG (NPOINT * SLOTS)   // pairs per batch = 67584

#define GRID 10
#define NC (GRID * GRID * GRID)   // 1000 cells per batch

// Scratch (device globals; no allocation allowed)
__device__ int    g_idx[PB * NPOINT * SLOTS];   // 1.08 MB
__device__ float4 g_ft4[PB * PN * 16];          // 8 MB, features transposed (B, N, C), float4 view
__device__ int    g_cellstart[PB][NC + 1];
__device__ float4 g_pts[PB * PN];               // cell-sorted coords, idx in .w

__device__ __forceinline__ int cell_of(float x) {
    int c = (int)(x * 10.0f);
    return min(max(c, 0), GRID - 1);
}

// ---------------------------------------------------------------------------
// Kernel 0: transpose features (B, C, N) -> (B, N, C), all-128-bit pipeline.
// Block handles a 64n x 64c tile. Thread (g,q): 4x LDG.128 (rows c=4g..4g+3,
// n-chunk q), register 4x4 transpose, 4x STS.128 into XOR-swizzled smem,
// then 4x (LDS.128 + STG.128) emit n-major rows. Conflict-free phases.
// ---------------------------------------------------------------------------
__global__ __launch_bounds__(256) void transpose_kernel(const float* __restrict__ feat) {
    __shared__ float4 t4[64 * 16];   // 16 KB, swizzled: [n][cg ^ ((n>>2)&15)]

    int b  = blockIdx.y;
    int n0 = blockIdx.x * 64;
    int tid = threadIdx.x;
    int g = tid >> 4;    // c-group 0..15 (channels 4g..4g+3)
    int q = tid & 15;    // n-chunk  0..15 (points n0+4q..n0+4q+3)

    const float4* fb4 = (const float4*)(feat + (size_t)b * PC * PN);
    float4 f[4];
#pragma unroll
    for (int p = 0; p < 4; p++)
        f[p] = fb4[(size_t)(4 * g + p) * (PN / 4) + (n0 >> 2) + q];

    // micro-transpose: v_j = (n = 4q+j, c = 4g..4g+3)
    {
        float4 v;
        v = make_float4(f[0].x, f[1].x, f[2].x, f[3].x);
        t4[(4 * q + 0) * 16 + (g ^ q)] = v;
        v = make_float4(f[0].y, f[1].y, f[2].y, f[3].y);
        t4[(4 * q + 1) * 16 + (g ^ q)] = v;
        v = make_float4(f[0].z, f[1].z, f[2].z, f[3].z);
        t4[(4 * q + 2) * 16 + (g ^ q)] = v;
        v = make_float4(f[0].w, f[1].w, f[2].w, f[3].w);
        t4[(4 * q + 3) * 16 + (g ^ q)] = v;
    }
    __syncthreads();

    float4* ob4 = g_ft4 + ((size_t)b * PN + n0) * 16;
#pragma unroll
    for (int k = 0; k < 4; k++) {
        int idx = k * 256 + tid;
        int n  = idx >> 4;
        int cg = idx & 15;
        ob4[n * 16 + cg] = t4[n * 16 + (cg ^ ((n >> 2) & 15))];
    }
}

// ---------------------------------------------------------------------------
// Kernel 1: fused grid build. One block per batch: histogram (smem atomics),
// two-level warp-shuffle scan, scatter from registers.
// ---------------------------------------------------------------------------
__global__ __launch_bounds__(1024) void grid_build_kernel(const float* __restrict__ xyz) {
    __shared__ int hist[NC];   // doubles as running cursor after scan
    __shared__ int wsum[32];

    int b = blockIdx.x, t = threadIdx.x;
    int lane = t & 31, w = t >> 5;

    for (int i = t; i < NC; i += 1024) hist[i] = 0;
    __syncthreads();

    const float* xb = xyz + (size_t)b * PN * 3;
    float px[8], py[8], pz[8];
    int   pc[8];
#pragma unroll
    for (int k = 0; k < 8; k++) {
        int i = t + k * 1024;
        px[k] = xb[i * 3 + 0];
        py[k] = xb[i * 3 + 1];
        pz[k] = xb[i * 3 + 2];
        pc[k] = (cell_of(pz[k]) * GRID + cell_of(py[k])) * GRID + cell_of(px[k]);
        atomicAdd(&hist[pc[k]], 1);
    }
    __syncthreads();

    int v = (t < NC) ? hist[t] : 0;
    int s = v;
#pragma unroll
    for (int off = 1; off < 32; off <<= 1) {
        int u = __shfl_up_sync(0xFFFFFFFFu, s, off);
        if (lane >= off) s += u;
    }
    if (lane == 31) wsum[w] = s;
    __syncthreads();
    if (w == 0) {
        int ws = wsum[lane];
#pragma unroll
        for (int off = 1; off < 32; off <<= 1) {
            int u = __shfl_up_sync(0xFFFFFFFFu, ws, off);
            if (lane >= off) ws += u;
        }
        wsum[lane] = ws;
    }
    __syncthreads();
    int incl = s + (w > 0 ? wsum[w - 1] : 0);
    int excl = incl - v;
    __syncthreads();
    if (t < NC) {
        g_cellstart[b][t + 1] = incl;
        if (t == 0) g_cellstart[b][0] = 0;
        hist[t] = excl;
    }
    __syncthreads();

    float4* pout = g_pts + ((size_t)b << 13);
#pragma unroll
    for (int k = 0; k < 8; k++) {
        int pos = atomicAdd(&hist[pc[k]], 1);
        pout[pos] = make_float4(px[k], py[k], pz[k], __int_as_float(t + k * 1024));
    }
}

// ---------------------------------------------------------------------------
// Warp bitonic sort of NR*32 ints (ascending), lane-major layout j = k*32+lane.
// ---------------------------------------------------------------------------
template <int NR>
__device__ __forceinline__ void bsort(int* r, int lane) {
    const int TOT = NR * 32;
#pragma unroll
    for (int size = 2; size <= TOT; size <<= 1) {
#pragma unroll
        for (int stride = size >> 1; stride > 0; stride >>= 1) {
            if (stride >= 32) {
                int ks = stride >> 5;
#pragma unroll
                for (int k = 0; k < NR; k++) {
                    if ((k & ks) == 0) {
                        int j = k * 32 + lane;
                        bool desc = (j & size) != 0;
                        int a = r[k], c = r[k + ks];
                        int lo = min(a, c), hi = max(a, c);
                        r[k]      = desc ? hi : lo;
                        r[k + ks] = desc ? lo : hi;
                    }
                }
            } else {
#pragma unroll
                for (int k = 0; k < NR; k++) {
                    int j = k * 32 + lane;
                    bool desc  = (j & size) != 0;
                    int  p     = __shfl_xor_sync(0xFFFFFFFFu, r[k], stride);
                    bool lower = (lane & stride) == 0;
                    r[k] = (lower != desc) ? min(r[k], p) : max(r[k], p);
                }
            }
        }
    }
}

// ---------------------------------------------------------------------------
// Kernel 2: grid ball query. One warp per centroid; scans <= 27 neighbor cells
// (x-contiguous rows), collects candidates, sorts ascending, takes 32 smallest.
// ---------------------------------------------------------------------------
#define BQ_WARPS 8

__global__ __launch_bounds__(BQ_WARPS * 32) void ballquery_grid_kernel(
    const float* __restrict__ new_xyz, const int* __restrict__ fps_idx) {
    __shared__ int slots[BQ_WARPS][128];

    int tid  = threadIdx.x;
    int w    = tid >> 5;
    int lane = tid & 31;
    int gc   = blockIdx.x * BQ_WARPS + w;
    int b    = gc / NPOINT;

    float cx = new_xyz[gc * 3 + 0];
    float cy = new_xyz[gc * 3 + 1];
    float cz = new_xyz[gc * 3 + 2];

    int icx = cell_of(cx), icy = cell_of(cy), icz = cell_of(cz);
    int xlo = max(icx - 1, 0), xhi = min(icx + 1, GRID - 1);
    int ylo = max(icy - 1, 0), yhi = min(icy + 1, GRID - 1);
    int zlo = max(icz - 1, 0), zhi = min(icz + 1, GRID - 1);

    const int*    cs  = g_cellstart[b];
    const float4* pts = g_pts + ((size_t)b << 13);

    int cnt = 0;
    for (int z = zlo; z <= zhi; z++) {
        for (int y = ylo; y <= yhi; y++) {
            int rowbase = (z * GRID + y) * GRID;
            int s = cs[rowbase + xlo];
            int e = cs[rowbase + xhi + 1];
            for (int base = s; base < e; base += 32) {
                int  i   = base + lane;
                bool inr = i < e;
                float4 p = inr ? pts[i] : make_float4(1e9f, 1e9f, 1e9f, 0.f);
                float dx = cx - p.x, dy = cy - p.y, dz = cz - p.z;
                // Match XLA's unfused left-to-right sum exactly (no FMA):
                float d2 = __fadd_rn(__fadd_rn(__fmul_rn(dx, dx), __fmul_rn(dy, dy)),
                                     __fmul_rn(dz, dz));
                bool valid = inr && (d2 < R2);
                unsigned m = __ballot_sync(0xFFFFFFFFu, valid);
                if (valid) {
                    int pos = cnt + __popc(m & ((1u << lane) - 1u));
                    if (pos < 128) slots[w][pos] = __float_as_int(p.w);
                }
                cnt += __popc(m);
            }
        }
    }
    __syncwarp();

    int cl = min(cnt, 128);
    int r[4];
#pragma unroll
    for (int k = 0; k < 4; k++) {
        int j = k * 32 + lane;
        r[k] = (j < cl) ? slots[w][j] : 0x7FFFFFFF;
    }
    if (cnt <= 32)      bsort<1>(r, lane);
    else if (cnt <= 64) bsort<2>(r, lane);
    else                bsort<4>(r, lane);

    int first = __shfl_sync(0xFFFFFFFFu, r[0], 0);
    int pad   = (cnt > 0) ? first : 0;
    int v     = (lane < cnt) ? r[0] : pad;

    int base = gc * SLOTS;
    if (lane == 0) g_idx[base] = fps_idx[gc];
    g_idx[base + 1 + lane] = v;
}

// ---------------------------------------------------------------------------
// Kernel 3: gather + center + concat, fully 128-bit pipeline.
// Output (B, 70, NPOINT, 33): ch 0-2 centered xyz, 3-5 dup, 6-69 features.
// Thread (g,q): 4x LDG.128 (pairs 4g..4g+3, chunk q), 4x4 register transpose,
// 4x STS.128 swizzled; consumer does LDS.128 + STG.128 per (channel, group).
// ---------------------------------------------------------------------------
#define GP 64
#define BPB (TPG / GP)   // 1056 blocks per batch

__global__ __launch_bounds__(256) void gather_kernel(
    const float* __restrict__ xyz, const float* __restrict__ new_xyz,
    float* __restrict__ out) {
    __shared__ float4 ft4[PC * 16];    // 16 KB, swizzled: [c][g ^ ((c>>2)&15)]
    __shared__ float4 cent4[3][16];    // centered xyz, float4 over pairs
    __shared__ int    sidx[GP];

    int bb  = blockIdx.x / BPB;
    int t0  = (blockIdx.x % BPB) * GP;
    int tid = threadIdx.x;

    if (tid < GP) {
        int t = t0 + tid;
        int j = t / SLOTS;
        int s = t - j * SLOTS;
        int iv = g_idx[(bb * NPOINT + j) * SLOTS + s];
        sidx[tid] = iv;
        const float* nz = new_xyz + ((size_t)bb * NPOINT + j) * 3;
        const float* pz = xyz + ((size_t)bb * PN + iv) * 3;
        ((float*)&cent4[0][0])[tid] = pz[0] - nz[0];
        ((float*)&cent4[1][0])[tid] = pz[1] - nz[1];
        ((float*)&cent4[2][0])[tid] = pz[2] - nz[2];
    }
    __syncthreads();

    // Stage: thread (g = pair-group 0..15, q = chunk 0..15)
    {
        int g = tid >> 4;
        int q = tid & 15;
        const float4* ftb4 = g_ft4 + (size_t)bb * PN * 16;
        float4 f[4];
#pragma unroll
        for (int p = 0; p < 4; p++)
            f[p] = ftb4[(size_t)sidx[4 * g + p] * 16 + q];
        float4 v;
        v = make_float4(f[0].x, f[1].x, f[2].x, f[3].x);
        ft4[(4 * q + 0) * 16 + (g ^ q)] = v;
        v = make_float4(f[0].y, f[1].y, f[2].y, f[3].y);
        ft4[(4 * q + 1) * 16 + (g ^ q)] = v;
        v = make_float4(f[0].z, f[1].z, f[2].z, f[3].z);
        ft4[(4 * q + 2) * 16 + (g ^ q)] = v;
        v = make_float4(f[0].w, f[1].w, f[2].w, f[3].w);
        ft4[(4 * q + 3) * 16 + (g ^ q)] = v;
    }
    __syncthreads();

    // Emit: 70 channels x 16 float4-groups, LDS.128 + STG.128.
    float* ob = out + (size_t)bb * 70 * TPG + t0;
    for (int k = tid; k < 70 * 16; k += 256) {
        int c = k >> 4;
        int g = k & 15;
        float4 v;
        if (c < 6) {
            v = cent4[c < 3 ? c : c - 3][g];
        } else {
            int cf = c - 6;
            v = ft4[cf * 16 + (g ^ ((cf >> 2) & 15))];
        }
        *(float4*)(ob + (size_t)c * TPG + 4 * g) = v;
    }
}

// ---------------------------------------------------------------------------
extern "C" void kernel_launch(void* const* d_in, const int* in_sizes, int n_in,
                              void* d_out, int out_size) {
    const float* xyz      = (const float*)d_in[0];   // (B, N, 3)
    const float* new_xyz  = (const float*)d_in[1];   // (B, NPOINT, 3)
    const float* features = (const float*)d_in[2];   // (B, C, N)
    const int*   fps_idx  = (const int*)d_in[3];     // (B, NPOINT)
    float* out = (float*)d_out;                      // (B, 70, NPOINT, 33)

    transpose_kernel<<<dim3(PN / 64, PB), 256>>>(features);
    grid_build_kernel<<<PB, 1024>>>(xyz);
    ballquery_grid_kernel<<<(PB * NPOINT) / BQ_WARPS, BQ_WARPS * 32>>>(new_xyz, fps_idx);
    gather_kernel<<<PB * BPB, 256>>>(xyz, new_xyz, out);
}

// round 7
// speedup vs baseline: 2.2625x; 1.0124x over previous
#include <cuda_runtime.h>

// Problem constants
#define PB 4
#define PN 8192
#define NPOINT 2048
#define PC 64
#define NS 32
#define SLOTS 33               // 1 (fps) + 32 samples
#define R2 (0.1f * 0.1f)
#define TPG (NPOINT * SLOTS)   // pairs per batch = 67584

#define GRID 10
#define NC (GRID * GRID * GRID)   // 1000 cells per batch

// Scratch (device globals; no allocation allowed)
__device__ int    g_idx[PB * NPOINT * SLOTS];   // 1.08 MB
__device__ float4 g_ft4[PB * PN * 16];          // 8 MB, features transposed (B, N, C), float4 view
__device__ int    g_cellstart[PB][NC + 1];
__device__ float4 g_pts[PB * PN];               // cell-sorted coords, idx in .w

__device__ __forceinline__ int cell_of(float x) {
    int c = (int)(x * 10.0f);
    return min(max(c, 0), GRID - 1);
}

// ---------------------------------------------------------------------------
// Kernel 0: transpose features (B, C, N) -> (B, N, C), all-128-bit pipeline.
// ---------------------------------------------------------------------------
__global__ __launch_bounds__(256) void transpose_kernel(const float* __restrict__ feat) {
    __shared__ float4 t4[64 * 16];   // 16 KB, swizzled: [n][cg ^ ((n>>2)&15)]

    int b  = blockIdx.y;
    int n0 = blockIdx.x * 64;
    int tid = threadIdx.x;
    int g = tid >> 4;    // c-group 0..15 (channels 4g..4g+3)
    int q = tid & 15;    // n-chunk  0..15 (points n0+4q..n0+4q+3)

    const float4* fb4 = (const float4*)(feat + (size_t)b * PC * PN);
    float4 f[4];
#pragma unroll
    for (int p = 0; p < 4; p++)
        f[p] = fb4[(size_t)(4 * g + p) * (PN / 4) + (n0 >> 2) + q];

    {
        float4 v;
        v = make_float4(f[0].x, f[1].x, f[2].x, f[3].x);
        t4[(4 * q + 0) * 16 + (g ^ q)] = v;
        v = make_float4(f[0].y, f[1].y, f[2].y, f[3].y);
        t4[(4 * q + 1) * 16 + (g ^ q)] = v;
        v = make_float4(f[0].z, f[1].z, f[2].z, f[3].z);
        t4[(4 * q + 2) * 16 + (g ^ q)] = v;
        v = make_float4(f[0].w, f[1].w, f[2].w, f[3].w);
        t4[(4 * q + 3) * 16 + (g ^ q)] = v;
    }
    __syncthreads();

    float4* ob4 = g_ft4 + ((size_t)b * PN + n0) * 16;
#pragma unroll
    for (int k = 0; k < 4; k++) {
        int idx = k * 256 + tid;
        int n  = idx >> 4;
        int cg = idx & 15;
        ob4[n * 16 + cg] = t4[n * 16 + (cg ^ ((n >> 2) & 15))];
    }
}

// ---------------------------------------------------------------------------
// Kernel 1: fused grid build. One block per batch. Vectorized point reads:
// thread t owns points 8t..8t+7 via 6x LDG.128.
// ---------------------------------------------------------------------------
__global__ __launch_bounds__(1024) void grid_build_kernel(const float* __restrict__ xyz) {
    __shared__ int hist[NC];   // doubles as running cursor after scan
    __shared__ int wsum[32];

    int b = blockIdx.x, t = threadIdx.x;
    int lane = t & 31, w = t >> 5;

    for (int i = t; i < NC; i += 1024) hist[i] = 0;
    __syncthreads();

    // 6 float4 = 8 points per thread.
    const float4* xb4 = (const float4*)(xyz + (size_t)b * PN * 3);
    float4 r4[6];
#pragma unroll
    for (int k = 0; k < 6; k++) r4[k] = xb4[t * 6 + k];
    const float* fp = (const float*)r4;

    int pc[8];
#pragma unroll
    for (int k = 0; k < 8; k++) {
        pc[k] = (cell_of(fp[3 * k + 2]) * GRID + cell_of(fp[3 * k + 1])) * GRID
                + cell_of(fp[3 * k + 0]);
        atomicAdd(&hist[pc[k]], 1);
    }
    __syncthreads();

    int v = (t < NC) ? hist[t] : 0;
    int s = v;
#pragma unroll
    for (int off = 1; off < 32; off <<= 1) {
        int u = __shfl_up_sync(0xFFFFFFFFu, s, off);
        if (lane >= off) s += u;
    }
    if (lane == 31) wsum[w] = s;
    __syncthreads();
    if (w == 0) {
        int ws = wsum[lane];
#pragma unroll
        for (int off = 1; off < 32; off <<= 1) {
            int u = __shfl_up_sync(0xFFFFFFFFu, ws, off);
            if (lane >= off) ws += u;
        }
        wsum[lane] = ws;
    }
    __syncthreads();
    int incl = s + (w > 0 ? wsum[w - 1] : 0);
    int excl = incl - v;
    __syncthreads();
    if (t < NC) {
        g_cellstart[b][t + 1] = incl;
        if (t == 0) g_cellstart[b][0] = 0;
        hist[t] = excl;
    }
    __syncthreads();

    float4* pout = g_pts + ((size_t)b << 13);
#pragma unroll
    for (int k = 0; k < 8; k++) {
        int pos = atomicAdd(&hist[pc[k]], 1);
        pout[pos] = make_float4(fp[3 * k + 0], fp[3 * k + 1], fp[3 * k + 2],
                                __int_as_float(t * 8 + k));
    }
}

// ---------------------------------------------------------------------------
// Warp bitonic sort of NR*32 ints (ascending), lane-major layout j = k*32+lane.
// ---------------------------------------------------------------------------
template <int NR>
__device__ __forceinline__ void bsort(int* r, int lane) {
    const int TOT = NR * 32;
#pragma unroll
    for (int size = 2; size <= TOT; size <<= 1) {
#pragma unroll
        for (int stride = size >> 1; stride > 0; stride >>= 1) {
            if (stride >= 32) {
                int ks = stride >> 5;
#pragma unroll
                for (int k = 0; k < NR; k++) {
                    if ((k & ks) == 0) {
                        int j = k * 32 + lane;
                        bool desc = (j & size) != 0;
                        int a = r[k], c = r[k + ks];
                        int lo = min(a, c), hi = max(a, c);
                        r[k]      = desc ? hi : lo;
                        r[k + ks] = desc ? lo : hi;
                    }
                }
            } else {
#pragma unroll
                for (int k = 0; k < NR; k++) {
                    int j = k * 32 + lane;
                    bool desc  = (j & size) != 0;
                    int  p     = __shfl_xor_sync(0xFFFFFFFFu, r[k], stride);
                    bool lower = (lane & stride) == 0;
                    r[k] = (lower != desc) ? min(r[k], p) : max(r[k], p);
                }
            }
        }
    }
}

// ---------------------------------------------------------------------------
// Kernel 2: grid ball query. One warp per centroid. All <=9 cell-row ranges
// preloaded in parallel by lanes 0..8 and broadcast via shuffle (no dependent
// loads inside the row loop).
// ---------------------------------------------------------------------------
#define BQ_WARPS 8

__global__ __launch_bounds__(BQ_WARPS * 32) void ballquery_grid_kernel(
    const float* __restrict__ new_xyz, const int* __restrict__ fps_idx) {
    __shared__ int slots[BQ_WARPS][128];

    int tid  = threadIdx.x;
    int w    = tid >> 5;
    int lane = tid & 31;
    int gc   = blockIdx.x * BQ_WARPS + w;
    int b    = gc / NPOINT;

    float cx = new_xyz[gc * 3 + 0];
    float cy = new_xyz[gc * 3 + 1];
    float cz = new_xyz[gc * 3 + 2];
    int fpsv = fps_idx[gc];

    int icx = cell_of(cx), icy = cell_of(cy), icz = cell_of(cz);
    int xlo = max(icx - 1, 0), xhi = min(icx + 1, GRID - 1);
    int ylo = max(icy - 1, 0), yhi = min(icy + 1, GRID - 1);
    int zlo = max(icz - 1, 0), zhi = min(icz + 1, GRID - 1);
    int ny_ = yhi - ylo + 1;
    int nrows = (zhi - zlo + 1) * ny_;

    const int*    cs  = g_cellstart[b];
    const float4* pts = g_pts + ((size_t)b << 13);

    // Parallel preload of all row ranges.
    int rs_ = 0, re_ = 0;
    if (lane < nrows) {
        int z = zlo + lane / ny_;
        int y = ylo + lane % ny_;
        int rb = (z * GRID + y) * GRID;
        rs_ = __ldg(&cs[rb + xlo]);
        re_ = __ldg(&cs[rb + xhi + 1]);
    }

    int cnt = 0;
    for (int rr = 0; rr < nrows; rr++) {
        int s = __shfl_sync(0xFFFFFFFFu, rs_, rr);
        int e = __shfl_sync(0xFFFFFFFFu, re_, rr);
        for (int base = s; base < e; base += 32) {
            int  i   = base + lane;
            float4 p = pts[min(i, PN - 1)];
            float dx = cx - p.x, dy = cy - p.y, dz = cz - p.z;
            // Match XLA's unfused left-to-right sum exactly (no FMA):
            float d2 = __fadd_rn(__fadd_rn(__fmul_rn(dx, dx), __fmul_rn(dy, dy)),
                                 __fmul_rn(dz, dz));
            bool valid = (i < e) && (d2 < R2);
            unsigned m = __ballot_sync(0xFFFFFFFFu, valid);
            if (valid) {
                int pos = cnt + __popc(m & ((1u << lane) - 1u));
                if (pos < 128) slots[w][pos] = __float_as_int(p.w);
            }
            cnt += __popc(m);
        }
    }
    __syncwarp();

    int cl = min(cnt, 128);
    int r[4];
#pragma unroll
    for (int k = 0; k < 4; k++) {
        int j = k * 32 + lane;
        r[k] = (j < cl) ? slots[w][j] : 0x7FFFFFFF;
    }
    if (cnt <= 32)      bsort<1>(r, lane);
    else if (cnt <= 64) bsort<2>(r, lane);
    else                bsort<4>(r, lane);

    int first = __shfl_sync(0xFFFFFFFFu, r[0], 0);
    int pad   = (cnt > 0) ? first : 0;
    int v     = (lane < cnt) ? r[0] : pad;

    int base = gc * SLOTS;
    if (lane == 0) g_idx[base] = fpsv;
    g_idx[base + 1 + lane] = v;
}

// ---------------------------------------------------------------------------
// Kernel 3: gather + center + concat. GP=128 pairs per 256-thread block:
// 8 LDG.128 in flight per thread during staging, swizzled 32-wide smem rows,
// LDS.128 + STG.128 emit. Output (B, 70, NPOINT, 33).
// ---------------------------------------------------------------------------
#define GP 128
#define BPB (TPG / GP)   // 528 blocks per batch

__global__ __launch_bounds__(256) void gather_kernel(
    const float* __restrict__ xyz, const float* __restrict__ new_xyz,
    float* __restrict__ out) {
    __shared__ float4 ft4[PC * 32];    // 32 KB, swizzled: [c][pg ^ ((c>>2)&15)]
    __shared__ float4 cent4[3][GP / 4];
    __shared__ int    sidx[GP];

    int bb  = blockIdx.x / BPB;
    int t0  = (blockIdx.x % BPB) * GP;
    int tid = threadIdx.x;

    if (tid < GP) {
        int t = t0 + tid;
        int j = t / SLOTS;
        int s = t - j * SLOTS;
        int iv = g_idx[(bb * NPOINT + j) * SLOTS + s];
        sidx[tid] = iv;
        const float* nz = new_xyz + ((size_t)bb * NPOINT + j) * 3;
        const float* pz = xyz + ((size_t)bb * PN + iv) * 3;
        ((float*)&cent4[0][0])[tid] = pz[0] - nz[0];
        ((float*)&cent4[1][0])[tid] = pz[1] - nz[1];
        ((float*)&cent4[2][0])[tid] = pz[2] - nz[2];
    }
    __syncthreads();

    // Stage: 2 transpose units per thread (unit = 4 pairs x 1 chunk).
    // Unit u: pg = u>>4 (0..31), q = u&15. 8 independent LDG.128 per thread.
    {
        const float4* ftb4 = g_ft4 + (size_t)bb * PN * 16;
        int u0 = tid, u1 = tid + 256;
        int pg0 = u0 >> 4, q0 = u0 & 15;
        int pg1 = u1 >> 4, q1 = u1 & 15;
        float4 f0[4], f1[4];
#pragma unroll
        for (int p = 0; p < 4; p++)
            f0[p] = ftb4[(size_t)sidx[4 * pg0 + p] * 16 + q0];
#pragma unroll
        for (int p = 0; p < 4; p++)
            f1[p] = ftb4[(size_t)sidx[4 * pg1 + p] * 16 + q1];

        float4 v;
        v = make_float4(f0[0].x, f0[1].x, f0[2].x, f0[3].x);
        ft4[(4 * q0 + 0) * 32 + (pg0 ^ q0)] = v;
        v = make_float4(f0[0].y, f0[1].y, f0[2].y, f0[3].y);
        ft4[(4 * q0 + 1) * 32 + (pg0 ^ q0)] = v;
        v = make_float4(f0[0].z, f0[1].z, f0[2].z, f0[3].z);
        ft4[(4 * q0 + 2) * 32 + (pg0 ^ q0)] = v;
        v = make_float4(f0[0].w, f0[1].w, f0[2].w, f0[3].w);
        ft4[(4 * q0 + 3) * 32 + (pg0 ^ q0)] = v;

        v = make_float4(f1[0].x, f1[1].x, f1[2].x, f1[3].x);
        ft4[(4 * q1 + 0) * 32 + (pg1 ^ q1)] = v;
        v = make_float4(f1[0].y, f1[1].y, f1[2].y, f1[3].y);
        ft4[(4 * q1 + 1) * 32 + (pg1 ^ q1)] = v;
        v = make_float4(f1[0].z, f1[1].z, f1[2].z, f1[3].z);
        ft4[(4 * q1 + 2) * 32 + (pg1 ^ q1)] = v;
        v = make_float4(f1[0].w, f1[1].w, f1[2].w, f1[3].w);
        ft4[(4 * q1 + 3) * 32 + (pg1 ^ q1)] = v;
    }
    __syncthreads();

    // Emit: 70 channels x 32 float4-groups, LDS.128 + STG.128.
    float* ob = out + (size_t)bb * 70 * TPG + t0;
    for (int k = tid; k < 70 * 32; k += 256) {
        int c = k >> 5;
        int g = k & 31;
        float4 v;
        if (c < 6) {
            v = cent4[c < 3 ? c : c - 3][g];
        } else {
            int cf = c - 6;
            v = ft4[cf * 32 + (g ^ ((cf >> 2) & 15))];
        }
        *(float4*)(ob + (size_t)c * TPG + 4 * g) = v;
    }
}

// ---------------------------------------------------------------------------
extern "C" void kernel_launch(void* const* d_in, const int* in_sizes, int n_in,
                              void* d_out, int out_size) {
    const float* xyz      = (const float*)d_in[0];   // (B, N, 3)
    const float* new_xyz  = (const float*)d_in[1];   // (B, NPOINT, 3)
    const float* features = (const float*)d_in[2];   // (B, C, N)
    const int*   fps_idx  = (const int*)d_in[3];     // (B, NPOINT)
    float* out = (float*)d_out;                      // (B, 70, NPOINT, 33)

    transpose_kernel<<<dim3(PN / 64, PB), 256>>>(features);
    grid_build_kernel<<<PB, 1024>>>(xyz);
    ballquery_grid_kernel<<<(PB * NPOINT) / BQ_WARPS, BQ_WARPS * 32>>>(new_xyz, fps_idx);
    gather_kernel<<<PB * BPB, 256>>>(xyz, new_xyz, out);
}